// round 9
// baseline (speedup 1.0000x reference)
#include <cuda_runtime.h>
#include <cuda_bf16.h>

// Problem constants
#define BB   64      // batch (inputs)
#define MM   256     // modes
#define KK   4096    // spatial (64*64)

#define KC      128  // K per CTA tile
#define KSPLIT  32   // KK / KC (tile-level)
#define NSPL    64   // dot-split granularity: 2 k-halves per tile
#define MT      64   // modes per CTA (2 per lane)
#define MTILES  4    // MM / MT
#define F4R     32   // float4 / ulonglong2 units per row (KC/4)
#define NTHR    512  // 16 warps: two 8-warp groups split the k-range
#define NCTA    (MTILES * KSPLIT)   // 128 CTAs, single wave
#define EPS_C   0.0009f

// Deterministic partial buffers (no cudaMalloc allowed)
__device__ __align__(16) float g_dot[NSPL * BB * MM];     // [s'][b][m]  4 MB
__device__ __align__(16) float g_fss[KSPLIT * BB];        // [ks][b]
__device__ __align__(16) float g_mss[KSPLIT * MM];        // [ks][m]
__device__ unsigned int g_cnt;    // arrival counter (reset by last CTA)
__device__ unsigned int g_go;     // release flag     (reset after tail)
__device__ unsigned int g_done;   // tail-done counter

__device__ __forceinline__ unsigned long long fma2(unsigned long long a,
                                                   unsigned long long b,
                                                   unsigned long long c) {
    unsigned long long d;
    asm("fma.rn.f32x2 %0, %1, %2, %3;" : "=l"(d) : "l"(a), "l"(b), "l"(c));
    return d;
}

__device__ __forceinline__ float2 ull2f2(unsigned long long u) {
    float2 f;
    f.x = __uint_as_float((unsigned int)u);
    f.y = __uint_as_float((unsigned int)(u >> 32));
    return f;
}

// Fused: GEMM partials + last-64-to-arrive finalize (one CTA per b).
__global__ __launch_bounds__(NTHR)
void fused_kernel(const float* __restrict__ inp,
                  const float* __restrict__ mds,
                  float* __restrict__ out) {
    __shared__ float As[BB * KC];    // 32 KB, k-major, unswizzled
    __shared__ float Bs[MT * KC];    // 32 KB, k-major, kq ^ (m&7) swizzle
    __shared__ float sd[2][MM];      // finalize combine
    __shared__ float red[8];
    __shared__ unsigned int s_rank;

    const int mt = blockIdx.x;
    const int ks = blockIdx.y;
    const int kbase = ks * KC;
    const int mbase = mt * MT;
    const int tid  = threadIdx.x;
    const int lane = tid & 31;
    const int w    = tid >> 5;       // 0..15
    const int ww   = w & 7;          // warp within k-group
    const int kh   = w >> 3;         // k-half 0/1

    float4* As4 = reinterpret_cast<float4*>(As);
    float4* Bs4 = reinterpret_cast<float4*>(Bs);

    // ---- stage A: 64 rows x 32 float4, coalesced ----
#pragma unroll
    for (int i = 0; i < 4; ++i) {
        int j  = i * NTHR + tid;
        int b  = j >> 5;
        int kq = j & 31;
        As4[b * F4R + kq] =
            *(reinterpret_cast<const float4*>(inp + (size_t)b * KK + kbase) + kq);
    }
    // ---- stage B: 64 rows x 32 float4, swizzled ----
#pragma unroll
    for (int i = 0; i < 4; ++i) {
        int j  = i * NTHR + tid;
        int m  = j >> 5;
        int kq = j & 31;
        Bs4[m * F4R + (kq ^ (m & 7))] =
            *(reinterpret_cast<const float4*>(mds + (size_t)(mbase + m) * KK + kbase) + kq);
    }
    __syncthreads();

    // ---- main loop: lane owns m = lane, lane+32; warp ww owns 8 b-rows;
    //      k-group kh covers kq 16*kh .. 16*kh+15 ----
    const int c = lane & 7;
    const ulonglong2* As2 = reinterpret_cast<const ulonglong2*>(As);
    const ulonglong2* Bs2 = reinterpret_cast<const ulonglong2*>(Bs);

    unsigned long long acc[8][2];
#pragma unroll
    for (int r = 0; r < 8; ++r) { acc[r][0] = 0ull; acc[r][1] = 0ull; }

    const int kq0 = kh << 4;
#pragma unroll 4
    for (int kq = 0; kq < 16; ++kq) {
        int j = kq0 + kq;
        ulonglong2 bv0 = Bs2[lane * F4R + (j ^ c)];          // 4 phases
        ulonglong2 bv1 = Bs2[(lane + 32) * F4R + (j ^ c)];   // 4 phases
#pragma unroll
        for (int r = 0; r < 8; ++r) {
            ulonglong2 av = As2[(8 * ww + r) * F4R + j];     // broadcast, 1 phase
            acc[r][0] = fma2(av.x, bv0.x, acc[r][0]);
            acc[r][0] = fma2(av.y, bv0.y, acc[r][0]);
            acc[r][1] = fma2(av.x, bv1.x, acc[r][1]);
            acc[r][1] = fma2(av.y, bv1.y, acc[r][1]);
        }
    }

    // ---- epilogue: per-half split slot s' = 2*ks + kh, coalesced stores ----
    const int sp = 2 * ks + kh;
#pragma unroll
    for (int r = 0; r < 8; ++r) {
        int b = 8 * ww + r;
        float2 e0 = ull2f2(acc[r][0]);
        float2 e1 = ull2f2(acc[r][1]);
        g_dot[((size_t)sp * BB + b) * MM + mbase + lane]      = e0.x + e0.y;
        g_dot[((size_t)sp * BB + b) * MM + mbase + 32 + lane] = e1.x + e1.y;
    }

    // ---- partial squared norms over the full tile (indexed by ks) ----
    // mode norms: 64 rows over 16 warps -> 4 rows each
#pragma unroll
    for (int r = 0; r < 4; ++r) {
        int m = 4 * w + r;
        float4 v = Bs4[m * F4R + (lane ^ (m & 7))];
        float s = v.x * v.x + v.y * v.y + v.z * v.z + v.w * v.w;
#pragma unroll
        for (int o = 16; o > 0; o >>= 1) s += __shfl_xor_sync(0xffffffffu, s, o);
        if (lane == 0) g_mss[ks * MM + mbase + m] = s;
    }
    // input norms: only mt==0 column writes; 64 rows over 16 warps
    if (mt == 0) {
#pragma unroll
        for (int r = 0; r < 4; ++r) {
            int b = 4 * w + r;
            float4 v = As4[b * F4R + lane];
            float s = v.x * v.x + v.y * v.y + v.z * v.z + v.w * v.w;
#pragma unroll
            for (int o = 16; o > 0; o >>= 1) s += __shfl_xor_sync(0xffffffffu, s, o);
            if (lane == 0) g_fss[ks * BB + b] = s;
        }
    }

    // ---- arrival: last 64 CTAs become finalizers (one b each) ----
    __syncthreads();
    if (tid == 0) {
        __threadfence();                                   // publish partials
        s_rank = atomicAdd(&g_cnt, 1u);                    // arrival rank
    }
    __syncthreads();
    const unsigned int rank = s_rank;

    if (rank < NCTA - BB) return;                          // early CTAs exit

    if (tid == 0) {
        if (rank == NCTA - 1) {                            // true last arriver
            g_cnt = 0;                                     // reset for next replay
            __threadfence();
            atomicExch(&g_go, 1u);                         // release
        } else {                                           // spin (acquire)
            unsigned int v;
            do {
                asm volatile("ld.acquire.gpu.u32 %0, [%1];"
                             : "=r"(v) : "l"(&g_go));
            } while (v == 0u);
        }
    }
    __syncthreads();

    // ---- finalize b: 512 threads = (mode m) x (split-half sq) ----
    const int b  = (int)rank - (NCTA - BB);
    const int m  = tid & 255;
    const int sq = tid >> 8;                               // 0/1

    float dot = 0.f;
#pragma unroll 8
    for (int i = 0; i < 32; ++i) {
        int s = sq * 32 + i;
        dot += g_dot[((size_t)s * BB + b) * MM + m];       // coalesced across m
    }
    sd[sq][m] = dot;
    __syncthreads();

    if (sq == 0) {
        dot = sd[0][m] + sd[1][m];
        float mss = 0.f, fss = 0.f;
#pragma unroll 8
        for (int s = 0; s < KSPLIT; ++s) {
            mss += g_mss[s * MM + m];
            fss += g_fss[s * BB + b];                      // uniform -> broadcast
        }

        float fn = sqrtf(fss);
        float mn = sqrtf(mss);
        float cc = dot / (fn * mn);
        float dn = sqrtf(fmaxf(2.f - 2.f * cc, 0.f));
        float lum = (2.f * fn * mn + EPS_C) / (fss + mss + EPS_C);
        float metric = (1.f - (2.f - dn) * 0.5f * sqrtf(lum)) * 2.f;

#pragma unroll
        for (int o = 16; o > 0; o >>= 1)
            metric = fminf(metric, __shfl_xor_sync(0xffffffffu, metric, o));
        if ((tid & 31) == 0) red[tid >> 5] = metric;
    }
    __syncthreads();
    if (tid == 0) {
        float v = red[0];
#pragma unroll
        for (int i = 1; i < 8; ++i) v = fminf(v, red[i]);
        out[b] = v;

        // last finished finalizer resets flags for next replay
        unsigned int d = atomicAdd(&g_done, 1u);
        if (d == BB - 1) {
            g_done = 0u;
            atomicExch(&g_go, 0u);
        }
    }
}

extern "C" void kernel_launch(void* const* d_in, const int* in_sizes, int n_in,
                              void* d_out, int out_size) {
    const float* inp = (const float*)d_in[0];
    const float* mds = (const float*)d_in[1];
    if (in_sizes[0] > in_sizes[1]) {   // identify by element count
        const float* t = inp; inp = mds; mds = t;
    }

    dim3 grid(MTILES, KSPLIT);         // 4 x 32 = 128 CTAs, single wave
    fused_kernel<<<grid, NTHR>>>(inp, mds, (float*)d_out);
}

// round 10
// speedup vs baseline: 1.1577x; 1.1577x over previous
#include <cuda_runtime.h>
#include <cuda_bf16.h>

// Problem constants
#define BB   64      // batch (inputs)
#define MM   256     // modes
#define KK   4096    // spatial (64*64)

#define KC      128  // K per CTA tile
#define KSPLIT  32   // KK / KC
#define MT      64   // modes per CTA
#define MTILES  4    // MM / MT
#define NTHR    256  // 8 warps
#define NCTA    (MTILES * KSPLIT)   // 128 CTAs, single co-resident wave
#define ROWF    132  // padded floats per smem row (bank-conflict-free fragments)
#define ROW4    33   // float4 units per row
#define SMEMB   (2 * BB * ROWF * 4) // A + B tiles, 67584 bytes
#define EPS_C   0.0009f

// Deterministic partial buffers (no cudaMalloc allowed)
__device__ __align__(16) float g_dot[KSPLIT * BB * MM];   // [s][b][m]  2 MB
__device__ __align__(16) float g_fss[KSPLIT * BB];        // [s][b]
__device__ __align__(16) float g_mss[KSPLIT * MM];        // [s][m]
__device__ unsigned int g_cnt;    // arrival counter (reset by last CTA)
__device__ unsigned int g_go;     // release flag     (reset after tail)
__device__ unsigned int g_done;   // tail-done counter

__device__ __forceinline__ unsigned int cvt_tf32(float x) {
    unsigned int u;
    asm("cvt.rna.tf32.f32 %0, %1;" : "=r"(u) : "f"(x));
    return u;
}

__device__ __forceinline__ void mma_tf32(float& d0, float& d1, float& d2, float& d3,
                                         unsigned int a0, unsigned int a1,
                                         unsigned int a2, unsigned int a3,
                                         unsigned int b0, unsigned int b1) {
    asm volatile(
        "mma.sync.aligned.m16n8k8.row.col.f32.tf32.tf32.f32 "
        "{%0,%1,%2,%3}, {%4,%5,%6,%7}, {%8,%9}, {%0,%1,%2,%3};"
        : "+f"(d0), "+f"(d1), "+f"(d2), "+f"(d3)
        : "r"(a0), "r"(a1), "r"(a2), "r"(a3), "r"(b0), "r"(b1));
}

// Fused: tf32 tensor-core GEMM partials + last-64-to-arrive finalize.
__global__ __launch_bounds__(NTHR)
void fused_kernel(const float* __restrict__ inp,
                  const float* __restrict__ mds,
                  float* __restrict__ out) {
    extern __shared__ unsigned int su[];
    unsigned int* Au = su;                 // A tile: 64 x 132 (tf32 bits)
    unsigned int* Bu = su + BB * ROWF;     // B tile: 64 x 132
    __shared__ float red[8];
    __shared__ unsigned int s_rank;

    const int mt = blockIdx.x;
    const int ks = blockIdx.y;
    const int kbase = ks * KC;
    const int mbase = mt * MT;
    const int tid  = threadIdx.x;
    const int lane = tid & 31;
    const int w    = tid >> 5;             // 0..7
    const int g    = lane >> 2;            // groupID 0..7
    const int tig  = lane & 3;             // thread-in-group 0..3

    uint4* Au4 = reinterpret_cast<uint4*>(Au);
    uint4* Bu4 = reinterpret_cast<uint4*>(Bu);

    // ---- stage A: 64 rows x 32 float4, coalesced, tf32-rounded ----
#pragma unroll
    for (int i = 0; i < 8; ++i) {
        int j  = i * NTHR + tid;
        int b  = j >> 5;
        int kq = j & 31;
        float4 v = *(reinterpret_cast<const float4*>(inp + (size_t)b * KK + kbase) + kq);
        Au4[b * ROW4 + kq] = make_uint4(cvt_tf32(v.x), cvt_tf32(v.y),
                                        cvt_tf32(v.z), cvt_tf32(v.w));
    }
    // ---- stage B: 64 rows x 32 float4 ----
#pragma unroll
    for (int i = 0; i < 8; ++i) {
        int j  = i * NTHR + tid;
        int m  = j >> 5;
        int kq = j & 31;
        float4 v = *(reinterpret_cast<const float4*>(mds + (size_t)(mbase + m) * KK + kbase) + kq);
        Bu4[m * ROW4 + kq] = make_uint4(cvt_tf32(v.x), cvt_tf32(v.y),
                                        cvt_tf32(v.z), cvt_tf32(v.w));
    }
    __syncthreads();

    // ---- tensor-core main loop ----
    // Warp w: m16-tile (w&3) x n32-half (w>>2). 16 k8-steps cover KC=128.
    const int r0 = (w & 3) * 16;           // A row base
    const int nh = (w >> 2) * 32;          // B col base (within 64-mode slice)

    float acc[4][4];
#pragma unroll
    for (int t = 0; t < 4; ++t)
#pragma unroll
        for (int i = 0; i < 4; ++i) acc[t][i] = 0.f;

#pragma unroll 4
    for (int kk = 0; kk < 16; ++kk) {
        const int acol = kk * 8 + tig;
        // A fragment (m16n8k8 tf32, row-major):
        // a0:(g, tig) a1:(g+8, tig) a2:(g, tig+4) a3:(g+8, tig+4)
        unsigned int a0 = Au[(r0 + g)     * ROWF + acol];
        unsigned int a1 = Au[(r0 + g + 8) * ROWF + acol];
        unsigned int a2 = Au[(r0 + g)     * ROWF + acol + 4];
        unsigned int a3 = Au[(r0 + g + 8) * ROWF + acol + 4];
#pragma unroll
        for (int t = 0; t < 4; ++t) {
            // B fragment (col): b0:(k=tig, n=g) b1:(k=tig+4, n=g); B[k][n] = Bu[n][k]
            int n = nh + t * 8 + g;
            unsigned int b0 = Bu[n * ROWF + kk * 8 + tig];
            unsigned int b1 = Bu[n * ROWF + kk * 8 + tig + 4];
            mma_tf32(acc[t][0], acc[t][1], acc[t][2], acc[t][3],
                     a0, a1, a2, a3, b0, b1);
        }
    }

    // ---- epilogue: D fragment c0/c1:(g, 2tig/2tig+1) c2/c3:(g+8, ...) ----
#pragma unroll
    for (int t = 0; t < 4; ++t) {
        int m = mbase + nh + t * 8 + 2 * tig;
        int b0r = r0 + g;
        float2 lo = make_float2(acc[t][0], acc[t][1]);
        float2 hi = make_float2(acc[t][2], acc[t][3]);
        *reinterpret_cast<float2*>(&g_dot[((size_t)ks * BB + b0r)     * MM + m]) = lo;
        *reinterpret_cast<float2*>(&g_dot[((size_t)ks * BB + b0r + 8) * MM + m]) = hi;
    }

    // ---- partial squared norms (from tf32-rounded tiles; warp per row) ----
    const float4* Af4 = reinterpret_cast<const float4*>(Au);
    const float4* Bf4 = reinterpret_cast<const float4*>(Bu);
#pragma unroll
    for (int r = 0; r < 8; ++r) {
        int m = 8 * w + r;
        float4 v = Bf4[m * ROW4 + lane];
        float s = v.x * v.x + v.y * v.y + v.z * v.z + v.w * v.w;
#pragma unroll
        for (int o = 16; o > 0; o >>= 1) s += __shfl_xor_sync(0xffffffffu, s, o);
        if (lane == 0) g_mss[ks * MM + mbase + m] = s;
    }
    if (mt == 0) {
#pragma unroll
        for (int r = 0; r < 8; ++r) {
            int b = 8 * w + r;
            float4 v = Af4[b * ROW4 + lane];
            float s = v.x * v.x + v.y * v.y + v.z * v.z + v.w * v.w;
#pragma unroll
            for (int o = 16; o > 0; o >>= 1) s += __shfl_xor_sync(0xffffffffu, s, o);
            if (lane == 0) g_fss[ks * BB + b] = s;
        }
    }

    // ---- arrival: last 64 CTAs become finalizers (one b each) ----
    __syncthreads();
    if (tid == 0) {
        __threadfence();                                   // publish partials
        s_rank = atomicAdd(&g_cnt, 1u);
    }
    __syncthreads();
    const unsigned int rank = s_rank;

    if (rank < NCTA - BB) return;

    if (tid == 0) {
        if (rank == NCTA - 1) {                            // true last arriver
            g_cnt = 0;                                     // reset for next replay
            __threadfence();
            atomicExch(&g_go, 1u);                         // release
        } else {
            unsigned int v;
            do {
                asm volatile("ld.acquire.gpu.u32 %0, [%1];"
                             : "=r"(v) : "l"(&g_go));
            } while (v == 0u);
        }
    }
    __syncthreads();

    // ---- finalize b = rank - (NCTA - BB); thread = mode m ----
    const int b = (int)rank - (NCTA - BB);
    const int m = tid;

    float dot = 0.f, mss = 0.f;
#pragma unroll 8
    for (int s = 0; s < KSPLIT; ++s) {
        dot += g_dot[((size_t)s * BB + b) * MM + m];       // coalesced across m
        mss += g_mss[s * MM + m];
    }
    float fss = 0.f;
#pragma unroll 8
    for (int s = 0; s < KSPLIT; ++s)
        fss += g_fss[s * BB + b];                          // uniform -> broadcast

    float fn = sqrtf(fss);
    float mn = sqrtf(mss);
    float cc = dot / (fn * mn);
    float dn = sqrtf(fmaxf(2.f - 2.f * cc, 0.f));
    float lum = (2.f * fn * mn + EPS_C) / (fss + mss + EPS_C);
    float metric = (1.f - (2.f - dn) * 0.5f * sqrtf(lum)) * 2.f;

#pragma unroll
    for (int o = 16; o > 0; o >>= 1)
        metric = fminf(metric, __shfl_xor_sync(0xffffffffu, metric, o));
    if ((tid & 31) == 0) red[tid >> 5] = metric;
    __syncthreads();
    if (tid == 0) {
        float v = red[0];
#pragma unroll
        for (int i = 1; i < 8; ++i) v = fminf(v, red[i]);
        out[b] = v;

        unsigned int d = atomicAdd(&g_done, 1u);           // last finalizer resets
        if (d == BB - 1) {
            g_done = 0u;
            atomicExch(&g_go, 0u);
        }
    }
}

extern "C" void kernel_launch(void* const* d_in, const int* in_sizes, int n_in,
                              void* d_out, int out_size) {
    const float* inp = (const float*)d_in[0];
    const float* mds = (const float*)d_in[1];
    if (in_sizes[0] > in_sizes[1]) {   // identify by element count
        const float* t = inp; inp = mds; mds = t;
    }

    cudaFuncSetAttribute(fused_kernel,
                         cudaFuncAttributeMaxDynamicSharedMemorySize, SMEMB);

    dim3 grid(MTILES, KSPLIT);         // 4 x 32 = 128 CTAs, single wave
    fused_kernel<<<grid, NTHR, SMEMB>>>(inp, mds, (float*)d_out);
}

// round 11
// speedup vs baseline: 1.3137x; 1.1348x over previous
#include <cuda_runtime.h>
#include <cuda_bf16.h>

// Problem constants
#define BB   64      // batch (inputs)
#define MM   256     // modes
#define KK   4096    // spatial (64*64)

#define KC      128  // K per CTA tile
#define KSPLIT  32   // KK / KC (norm granularity)
#define NSPL    64   // dot-split granularity (2 k-halves per tile)
#define MT      64   // modes per CTA
#define MTILES  4    // MM / MT
#define NTHR    256  // 8 warps = 2(m) x 2(n) x 2(k-half)
#define NCTA    (MTILES * KSPLIT)   // 128 CTAs, single co-resident wave
#define ROWF    132  // padded floats per smem row (conflict-free fragments)
#define ROW4    33   // float4 units per row
#define SMEMB   (2 * BB * ROWF * 4) // A + B tiles, 67584 bytes
#define EPS_C   0.0009f

// Deterministic partial buffers (no cudaMalloc allowed)
__device__ __align__(16) float g_dot[NSPL * BB * MM];     // [sp][b][m]  4 MB
__device__ __align__(16) float g_fss[KSPLIT * BB];        // [ks][b]
__device__ __align__(16) float g_mss[KSPLIT * MM];        // [ks][m]
__device__ unsigned int g_cnt;    // arrival counter (reset by last CTA)
__device__ unsigned int g_go;     // release flag     (reset after tail)
__device__ unsigned int g_done;   // tail-done counter

__device__ __forceinline__ unsigned int cvt_tf32(float x) {
    unsigned int u;
    asm("cvt.rna.tf32.f32 %0, %1;" : "=r"(u) : "f"(x));
    return u;
}

__device__ __forceinline__ void mma_tf32(float& d0, float& d1, float& d2, float& d3,
                                         unsigned int a0, unsigned int a1,
                                         unsigned int a2, unsigned int a3,
                                         unsigned int b0, unsigned int b1) {
    asm volatile(
        "mma.sync.aligned.m16n8k8.row.col.f32.tf32.tf32.f32 "
        "{%0,%1,%2,%3}, {%4,%5,%6,%7}, {%8,%9}, {%0,%1,%2,%3};"
        : "+f"(d0), "+f"(d1), "+f"(d2), "+f"(d3)
        : "r"(a0), "r"(a1), "r"(a2), "r"(a3), "r"(b0), "r"(b1));
}

// Fused: tf32 tensor-core GEMM partials + last-64-to-arrive finalize.
__global__ __launch_bounds__(NTHR)
void fused_kernel(const float* __restrict__ inp,
                  const float* __restrict__ mds,
                  float* __restrict__ out) {
    extern __shared__ unsigned int su[];
    unsigned int* Au = su;                 // A tile: 64 x 132 (tf32 bits)
    unsigned int* Bu = su + BB * ROWF;     // B tile: 64 x 132
    __shared__ float4 sd4[4][MM / 4];      // finalize: dot combine
    __shared__ float4 sm4[4][MM / 4];      // finalize: mss combine
    __shared__ float  sf[4];
    __shared__ float  red[2];
    __shared__ unsigned int s_rank;

    const int mt = blockIdx.x;
    const int ks = blockIdx.y;
    const int kbase = ks * KC;
    const int mbase = mt * MT;
    const int tid  = threadIdx.x;
    const int lane = tid & 31;
    const int w    = tid >> 5;             // 0..7
    const int g    = lane >> 2;            // groupID 0..7
    const int tig  = lane & 3;             // thread-in-group 0..3

    uint4* Au4 = reinterpret_cast<uint4*>(Au);
    uint4* Bu4 = reinterpret_cast<uint4*>(Bu);

    // ---- stage A: 64 rows x 32 float4, coalesced, tf32-rounded ----
#pragma unroll
    for (int i = 0; i < 8; ++i) {
        int j  = i * NTHR + tid;
        int b  = j >> 5;
        int kq = j & 31;
        float4 v = *(reinterpret_cast<const float4*>(inp + (size_t)b * KK + kbase) + kq);
        Au4[b * ROW4 + kq] = make_uint4(cvt_tf32(v.x), cvt_tf32(v.y),
                                        cvt_tf32(v.z), cvt_tf32(v.w));
    }
    // ---- stage B: 64 rows x 32 float4 ----
#pragma unroll
    for (int i = 0; i < 8; ++i) {
        int j  = i * NTHR + tid;
        int m  = j >> 5;
        int kq = j & 31;
        float4 v = *(reinterpret_cast<const float4*>(mds + (size_t)(mbase + m) * KK + kbase) + kq);
        Bu4[m * ROW4 + kq] = make_uint4(cvt_tf32(v.x), cvt_tf32(v.y),
                                        cvt_tf32(v.z), cvt_tf32(v.w));
    }
    __syncthreads();

    // ---- tensor-core main loop: m32 x n32 x k64 warp tiles ----
    const int kh = w >> 2;                 // k-half 0/1
    const int wm = w & 1;                  // m-half
    const int wn = (w >> 1) & 1;           // n-half
    const int r0 = wm * 32;                // A row base
    const int n0 = wn * 32;                // B col base (within 64-mode slice)
    const int kb = kh * 64;                // k base (floats)

    float acc[2][4][4];                    // [mi][t][frag]
#pragma unroll
    for (int mi = 0; mi < 2; ++mi)
#pragma unroll
        for (int t = 0; t < 4; ++t)
#pragma unroll
            for (int i = 0; i < 4; ++i) acc[mi][t][i] = 0.f;

#pragma unroll 4
    for (int kk = 0; kk < 8; ++kk) {
        const int acol = kb + kk * 8 + tig;
        unsigned int a[2][4];
#pragma unroll
        for (int mi = 0; mi < 2; ++mi) {
            int row = r0 + 16 * mi + g;
            a[mi][0] = Au[row       * ROWF + acol];
            a[mi][1] = Au[(row + 8) * ROWF + acol];
            a[mi][2] = Au[row       * ROWF + acol + 4];
            a[mi][3] = Au[(row + 8) * ROWF + acol + 4];
        }
#pragma unroll
        for (int t = 0; t < 4; ++t) {
            int n = n0 + t * 8 + g;
            unsigned int b0 = Bu[n * ROWF + kb + kk * 8 + tig];
            unsigned int b1 = Bu[n * ROWF + kb + kk * 8 + tig + 4];
#pragma unroll
            for (int mi = 0; mi < 2; ++mi)
                mma_tf32(acc[mi][t][0], acc[mi][t][1], acc[mi][t][2], acc[mi][t][3],
                         a[mi][0], a[mi][1], a[mi][2], a[mi][3], b0, b1);
        }
    }

    // ---- epilogue: per-k-half split slot sp = 2*ks + kh ----
    const int sp = 2 * ks + kh;
#pragma unroll
    for (int mi = 0; mi < 2; ++mi)
#pragma unroll
        for (int t = 0; t < 4; ++t) {
            int row = r0 + 16 * mi + g;
            int m = mbase + n0 + t * 8 + 2 * tig;
            *reinterpret_cast<float2*>(&g_dot[((size_t)sp * BB + row)     * MM + m]) =
                make_float2(acc[mi][t][0], acc[mi][t][1]);
            *reinterpret_cast<float2*>(&g_dot[((size_t)sp * BB + row + 8) * MM + m]) =
                make_float2(acc[mi][t][2], acc[mi][t][3]);
        }

    // ---- partial squared norms (from tf32-rounded tiles; warp per row) ----
    const float4* Af4 = reinterpret_cast<const float4*>(Au);
    const float4* Bf4 = reinterpret_cast<const float4*>(Bu);
#pragma unroll
    for (int r = 0; r < 8; ++r) {
        int m = 8 * w + r;
        float4 v = Bf4[m * ROW4 + lane];
        float s = v.x * v.x + v.y * v.y + v.z * v.z + v.w * v.w;
#pragma unroll
        for (int o = 16; o > 0; o >>= 1) s += __shfl_xor_sync(0xffffffffu, s, o);
        if (lane == 0) g_mss[ks * MM + mbase + m] = s;
    }
    if (mt == 0) {
#pragma unroll
        for (int r = 0; r < 8; ++r) {
            int b = 8 * w + r;
            float4 v = Af4[b * ROW4 + lane];
            float s = v.x * v.x + v.y * v.y + v.z * v.z + v.w * v.w;
#pragma unroll
            for (int o = 16; o > 0; o >>= 1) s += __shfl_xor_sync(0xffffffffu, s, o);
            if (lane == 0) g_fss[ks * BB + b] = s;
        }
    }

    // ---- arrival: last 64 CTAs become finalizers (one b each) ----
    __syncthreads();
    if (tid == 0) {
        __threadfence();                                   // publish partials
        s_rank = atomicAdd(&g_cnt, 1u);
    }
    __syncthreads();
    const unsigned int rank = s_rank;

    if (rank < NCTA - BB) return;

    if (tid == 0) {
        if (rank == NCTA - 1) {                            // true last arriver
            g_cnt = 0;                                     // reset for next replay
            __threadfence();
            atomicExch(&g_go, 1u);                         // release
        } else {
            unsigned int v;
            do {
                asm volatile("ld.acquire.gpu.u32 %0, [%1];"
                             : "=r"(v) : "l"(&g_go));
            } while (v == 0u);
        }
    }
    __syncthreads();

    // ---- finalize b: thread = (m-quad q, split-group sg) ----
    const int b  = (int)rank - (NCTA - BB);
    const int q  = tid & 63;                               // m-quad 0..63
    const int sg = tid >> 6;                               // group 0..3

    const float4* dot4 = reinterpret_cast<const float4*>(g_dot);
    const float4* mss4 = reinterpret_cast<const float4*>(g_mss);

    float4 d = make_float4(0.f, 0.f, 0.f, 0.f);
#pragma unroll
    for (int i = 0; i < 16; ++i) {                         // 16 of 64 dot-splits
        int s = sg * 16 + i;
        float4 v = dot4[((size_t)s * BB + b) * (MM / 4) + q];
        d.x += v.x; d.y += v.y; d.z += v.z; d.w += v.w;
    }
    float4 ms = make_float4(0.f, 0.f, 0.f, 0.f);
    float fs = 0.f;
#pragma unroll
    for (int i = 0; i < 8; ++i) {                          // 8 of 32 norm-splits
        int s = sg * 8 + i;
        float4 v = mss4[s * (MM / 4) + q];
        ms.x += v.x; ms.y += v.y; ms.z += v.z; ms.w += v.w;
        fs += g_fss[s * BB + b];                           // uniform -> broadcast
    }
    sd4[sg][q] = d;
    sm4[sg][q] = ms;
    if (q == 0) sf[sg] = fs;
    __syncthreads();

    if (sg == 0) {
        float4 d0 = sd4[0][q], d1 = sd4[1][q], d2 = sd4[2][q], d3 = sd4[3][q];
        float4 m0 = sm4[0][q], m1 = sm4[1][q], m2 = sm4[2][q], m3 = sm4[3][q];
        float dot[4] = { d0.x + d1.x + d2.x + d3.x, d0.y + d1.y + d2.y + d3.y,
                         d0.z + d1.z + d2.z + d3.z, d0.w + d1.w + d2.w + d3.w };
        float mss[4] = { m0.x + m1.x + m2.x + m3.x, m0.y + m1.y + m2.y + m3.y,
                         m0.z + m1.z + m2.z + m3.z, m0.w + m1.w + m2.w + m3.w };
        float fss = sf[0] + sf[1] + sf[2] + sf[3];
        float fn = sqrtf(fss);

        float best = 3.4e38f;
#pragma unroll
        for (int i = 0; i < 4; ++i) {
            float mn = sqrtf(mss[i]);
            float cc = dot[i] / (fn * mn);
            float dn = sqrtf(fmaxf(2.f - 2.f * cc, 0.f));
            float lum = (2.f * fn * mn + EPS_C) / (fss + mss[i] + EPS_C);
            float metric = (1.f - (2.f - dn) * 0.5f * sqrtf(lum)) * 2.f;
            best = fminf(best, metric);
        }
#pragma unroll
        for (int o = 16; o > 0; o >>= 1)
            best = fminf(best, __shfl_xor_sync(0xffffffffu, best, o));
        if ((tid & 31) == 0) red[tid >> 5] = best;
    }
    __syncthreads();
    if (tid == 0) {
        out[b] = fminf(red[0], red[1]);

        unsigned int dn = atomicAdd(&g_done, 1u);          // last finalizer resets
        if (dn == BB - 1) {
            g_done = 0u;
            atomicExch(&g_go, 0u);
        }
    }
}

extern "C" void kernel_launch(void* const* d_in, const int* in_sizes, int n_in,
                              void* d_out, int out_size) {
    const float* inp = (const float*)d_in[0];
    const float* mds = (const float*)d_in[1];
    if (in_sizes[0] > in_sizes[1]) {   // identify by element count
        const float* t = inp; inp = mds; mds = t;
    }

    cudaFuncSetAttribute(fused_kernel,
                         cudaFuncAttributeMaxDynamicSharedMemorySize, SMEMB);

    dim3 grid(MTILES, KSPLIT);         // 4 x 32 = 128 CTAs, single wave
    fused_kernel<<<grid, NTHR, SMEMB>>>(inp, mds, (float*)d_out);
}

// round 12
// speedup vs baseline: 1.3467x; 1.0251x over previous
#include <cuda_runtime.h>
#include <cuda_bf16.h>

// Problem constants
#define BB   64      // batch (inputs)
#define MM   256     // modes
#define KK   4096    // spatial (64*64)

#define KC      128  // K per CTA tile
#define KSPLIT  32   // KK / KC (norm granularity)
#define NSPL    64   // dot-split granularity (2 k-halves per tile)
#define MT      64   // modes per CTA
#define MTILES  4    // MM / MT
#define NTHR    256  // 8 warps = 2(m) x 2(n) x 2(k-half)
#define NCTA    (MTILES * KSPLIT)   // 128 CTAs, single co-resident wave
#define ROWF    132  // padded floats per smem row (conflict-free fragments)
#define ROW4    33   // float4 units per row
#define SMEMB   (2 * BB * ROWF * 4) // A + B tiles, 67584 bytes
#define EPS_C   0.0009f

// Deterministic partial buffers (no cudaMalloc allowed)
__device__ __align__(16) float g_dot[NSPL * BB * MM];     // [sp][b][m]  4 MB
__device__ __align__(16) float g_fss[KSPLIT * BB];        // [ks][b]
__device__ __align__(16) float g_mss[KSPLIT * MM];        // [ks][m]
__device__ unsigned int g_cnt;    // arrival counter (reset by last CTA)
__device__ unsigned int g_go;     // release flag     (reset after tail)
__device__ unsigned int g_done;   // tail-done counter

__device__ __forceinline__ void cp_async16(void* smem, const void* gmem) {
    unsigned int s = (unsigned int)__cvta_generic_to_shared(smem);
    asm volatile("cp.async.cg.shared.global [%0], [%1], 16;"
                 :: "r"(s), "l"(gmem));
}

// mma.tf32 fed with RAW f32 bits (HW reads sign/exp/top-10-mantissa =
// round-toward-zero tf32; CUTLASS-sanctioned mode).
__device__ __forceinline__ void mma_tf32(float& d0, float& d1, float& d2, float& d3,
                                         unsigned int a0, unsigned int a1,
                                         unsigned int a2, unsigned int a3,
                                         unsigned int b0, unsigned int b1) {
    asm volatile(
        "mma.sync.aligned.m16n8k8.row.col.f32.tf32.tf32.f32 "
        "{%0,%1,%2,%3}, {%4,%5,%6,%7}, {%8,%9}, {%0,%1,%2,%3};"
        : "+f"(d0), "+f"(d1), "+f"(d2), "+f"(d3)
        : "r"(a0), "r"(a1), "r"(a2), "r"(a3), "r"(b0), "r"(b1));
}

// Fused: tf32 tensor-core GEMM partials + last-64-to-arrive finalize.
__global__ __launch_bounds__(NTHR)
void fused_kernel(const float* __restrict__ inp,
                  const float* __restrict__ mds,
                  float* __restrict__ out) {
    extern __shared__ unsigned int su[];
    unsigned int* Au = su;                 // A tile: 64 x 132 raw f32 bits
    unsigned int* Bu = su + BB * ROWF;     // B tile: 64 x 132
    __shared__ float4 sd4[4][MM / 4];      // finalize: dot combine
    __shared__ float4 sm4[4][MM / 4];      // finalize: mss combine
    __shared__ float  sf[4];
    __shared__ float  red[2];
    __shared__ unsigned int s_rank;

    const int mt = blockIdx.x;
    const int ks = blockIdx.y;
    const int kbase = ks * KC;
    const int mbase = mt * MT;
    const int tid  = threadIdx.x;
    const int lane = tid & 31;
    const int w    = tid >> 5;             // 0..7
    const int g    = lane >> 2;            // groupID 0..7
    const int tig  = lane & 3;             // thread-in-group 0..3

    uint4* Au4 = reinterpret_cast<uint4*>(Au);
    uint4* Bu4 = reinterpret_cast<uint4*>(Bu);

    // ---- stage A+B via cp.async (no LDG-wait, no CVT, no STS chain) ----
#pragma unroll
    for (int i = 0; i < 8; ++i) {
        int j  = i * NTHR + tid;
        int b  = j >> 5;
        int kq = j & 31;
        cp_async16(&Au4[b * ROW4 + kq],
                   reinterpret_cast<const float4*>(inp + (size_t)b * KK + kbase) + kq);
    }
#pragma unroll
    for (int i = 0; i < 8; ++i) {
        int j  = i * NTHR + tid;
        int m  = j >> 5;
        int kq = j & 31;
        cp_async16(&Bu4[m * ROW4 + kq],
                   reinterpret_cast<const float4*>(mds + (size_t)(mbase + m) * KK + kbase) + kq);
    }
    asm volatile("cp.async.commit_group;");
    asm volatile("cp.async.wait_group 0;");
    __syncthreads();

    // ---- tensor-core main loop: m32 x n32 x k64 warp tiles ----
    const int kh = w >> 2;                 // k-half 0/1
    const int wm = w & 1;                  // m-half
    const int wn = (w >> 1) & 1;           // n-half
    const int r0 = wm * 32;                // A row base
    const int n0 = wn * 32;                // B col base (within 64-mode slice)
    const int kb = kh * 64;                // k base (floats)

    float acc[2][4][4];                    // [mi][t][frag]
#pragma unroll
    for (int mi = 0; mi < 2; ++mi)
#pragma unroll
        for (int t = 0; t < 4; ++t)
#pragma unroll
            for (int i = 0; i < 4; ++i) acc[mi][t][i] = 0.f;

#pragma unroll 4
    for (int kk = 0; kk < 8; ++kk) {
        const int acol = kb + kk * 8 + tig;
        unsigned int a[2][4];
#pragma unroll
        for (int mi = 0; mi < 2; ++mi) {
            int row = r0 + 16 * mi + g;
            a[mi][0] = Au[row       * ROWF + acol];
            a[mi][1] = Au[(row + 8) * ROWF + acol];
            a[mi][2] = Au[row       * ROWF + acol + 4];
            a[mi][3] = Au[(row + 8) * ROWF + acol + 4];
        }
#pragma unroll
        for (int t = 0; t < 4; ++t) {
            int n = n0 + t * 8 + g;
            unsigned int b0 = Bu[n * ROWF + kb + kk * 8 + tig];
            unsigned int b1 = Bu[n * ROWF + kb + kk * 8 + tig + 4];
#pragma unroll
            for (int mi = 0; mi < 2; ++mi)
                mma_tf32(acc[mi][t][0], acc[mi][t][1], acc[mi][t][2], acc[mi][t][3],
                         a[mi][0], a[mi][1], a[mi][2], a[mi][3], b0, b1);
        }
    }

    // ---- epilogue: per-k-half split slot sp = 2*ks + kh ----
    const int sp = 2 * ks + kh;
#pragma unroll
    for (int mi = 0; mi < 2; ++mi)
#pragma unroll
        for (int t = 0; t < 4; ++t) {
            int row = r0 + 16 * mi + g;
            int m = mbase + n0 + t * 8 + 2 * tig;
            *reinterpret_cast<float2*>(&g_dot[((size_t)sp * BB + row)     * MM + m]) =
                make_float2(acc[mi][t][0], acc[mi][t][1]);
            *reinterpret_cast<float2*>(&g_dot[((size_t)sp * BB + row + 8) * MM + m]) =
                make_float2(acc[mi][t][2], acc[mi][t][3]);
        }

    // ---- partial squared norms from RAW f32 tiles (warp per row) ----
    const float4* Af4 = reinterpret_cast<const float4*>(Au);
    const float4* Bf4 = reinterpret_cast<const float4*>(Bu);
#pragma unroll
    for (int r = 0; r < 8; ++r) {
        int m = 8 * w + r;
        float4 v = Bf4[m * ROW4 + lane];
        float s = v.x * v.x + v.y * v.y + v.z * v.z + v.w * v.w;
#pragma unroll
        for (int o = 16; o > 0; o >>= 1) s += __shfl_xor_sync(0xffffffffu, s, o);
        if (lane == 0) g_mss[ks * MM + mbase + m] = s;
    }
    if (mt == 0) {
#pragma unroll
        for (int r = 0; r < 8; ++r) {
            int b = 8 * w + r;
            float4 v = Af4[b * ROW4 + lane];
            float s = v.x * v.x + v.y * v.y + v.z * v.z + v.w * v.w;
#pragma unroll
            for (int o = 16; o > 0; o >>= 1) s += __shfl_xor_sync(0xffffffffu, s, o);
            if (lane == 0) g_fss[ks * BB + b] = s;
        }
    }

    // ---- arrival: last 64 CTAs become finalizers (one b each) ----
    __syncthreads();
    if (tid == 0) {
        __threadfence();                                   // publish partials
        s_rank = atomicAdd(&g_cnt, 1u);
    }
    __syncthreads();
    const unsigned int rank = s_rank;

    if (rank < NCTA - BB) return;

    if (tid == 0) {
        if (rank == NCTA - 1) {                            // true last arriver
            g_cnt = 0;                                     // reset for next replay
            __threadfence();
            atomicExch(&g_go, 1u);                         // release
        } else {
            unsigned int v;
            do {
                asm volatile("ld.acquire.gpu.u32 %0, [%1];"
                             : "=r"(v) : "l"(&g_go));
            } while (v == 0u);
        }
    }
    __syncthreads();

    // ---- finalize b: thread = (m-quad q, split-group sg) ----
    const int b  = (int)rank - (NCTA - BB);
    const int q  = tid & 63;                               // m-quad 0..63
    const int sg = tid >> 6;                               // group 0..3

    const float4* dot4 = reinterpret_cast<const float4*>(g_dot);
    const float4* mss4 = reinterpret_cast<const float4*>(g_mss);

    float4 d = make_float4(0.f, 0.f, 0.f, 0.f);
#pragma unroll
    for (int i = 0; i < 16; ++i) {                         // 16 of 64 dot-splits
        int s = sg * 16 + i;
        float4 v = dot4[((size_t)s * BB + b) * (MM / 4) + q];
        d.x += v.x; d.y += v.y; d.z += v.z; d.w += v.w;
    }
    float4 ms = make_float4(0.f, 0.f, 0.f, 0.f);
    float fs = 0.f;
#pragma unroll
    for (int i = 0; i < 8; ++i) {                          // 8 of 32 norm-splits
        int s = sg * 8 + i;
        float4 v = mss4[s * (MM / 4) + q];
        ms.x += v.x; ms.y += v.y; ms.z += v.z; ms.w += v.w;
        fs += g_fss[s * BB + b];                           // uniform -> broadcast
    }
    sd4[sg][q] = d;
    sm4[sg][q] = ms;
    if (q == 0) sf[sg] = fs;
    __syncthreads();

    if (sg == 0) {
        float4 d0 = sd4[0][q], d1 = sd4[1][q], d2 = sd4[2][q], d3 = sd4[3][q];
        float4 m0 = sm4[0][q], m1 = sm4[1][q], m2 = sm4[2][q], m3 = sm4[3][q];
        float dot[4] = { d0.x + d1.x + d2.x + d3.x, d0.y + d1.y + d2.y + d3.y,
                         d0.z + d1.z + d2.z + d3.z, d0.w + d1.w + d2.w + d3.w };
        float mss[4] = { m0.x + m1.x + m2.x + m3.x, m0.y + m1.y + m2.y + m3.y,
                         m0.z + m1.z + m2.z + m3.z, m0.w + m1.w + m2.w + m3.w };
        float fss = sf[0] + sf[1] + sf[2] + sf[3];
        float fn = sqrtf(fss);

        float best = 3.4e38f;
#pragma unroll
        for (int i = 0; i < 4; ++i) {
            float mn = sqrtf(mss[i]);
            float cc = dot[i] / (fn * mn);
            float dn = sqrtf(fmaxf(2.f - 2.f * cc, 0.f));
            float lum = (2.f * fn * mn + EPS_C) / (fss + mss[i] + EPS_C);
            float metric = (1.f - (2.f - dn) * 0.5f * sqrtf(lum)) * 2.f;
            best = fminf(best, metric);
        }
#pragma unroll
        for (int o = 16; o > 0; o >>= 1)
            best = fminf(best, __shfl_xor_sync(0xffffffffu, best, o));
        if ((tid & 31) == 0) red[tid >> 5] = best;
    }
    __syncthreads();
    if (tid == 0) {
        out[b] = fminf(red[0], red[1]);

        unsigned int dn = atomicAdd(&g_done, 1u);          // last finalizer resets
        if (dn == BB - 1) {
            g_done = 0u;
            atomicExch(&g_go, 0u);
        }
    }
}

extern "C" void kernel_launch(void* const* d_in, const int* in_sizes, int n_in,
                              void* d_out, int out_size) {
    const float* inp = (const float*)d_in[0];
    const float* mds = (const float*)d_in[1];
    if (in_sizes[0] > in_sizes[1]) {   // identify by element count
        const float* t = inp; inp = mds; mds = t;
    }

    cudaFuncSetAttribute(fused_kernel,
                         cudaFuncAttributeMaxDynamicSharedMemorySize, SMEMB);

    dim3 grid(MTILES, KSPLIT);         // 4 x 32 = 128 CTAs, single wave
    fused_kernel<<<grid, NTHR, SMEMB>>>(inp, mds, (float*)d_out);
}